// round 8
// baseline (speedup 1.0000x reference)
#include <cuda_runtime.h>
#include <cuda_fp16.h>
#include <cstdint>

// ---------------- problem constants ----------------
#define BLn    8192      // B * L
#define LSEQ   4096
#define DIMI   2048
#define DINn   8512      // 2*HID + 2*G*N + H
#define HIDC   4096
#define CONVD  4352      // HID + 2*G*N
#define NHh    64        // heads
#define PD     64        // head dim
#define NS     128       // state dim
#define QC     128       // chunk len
#define NCT    64        // total chunks = B * (L/Q)

// ---------------- scratch (device globals; allocation-free rule) ----------------
__device__ float g_zx[(size_t)BLn * DINn];        // in-proj output (z | xBC | dt_raw)
__device__ float g_conv[(size_t)BLn * CONVD];     // conv+silu output (xs | B | C)
__device__ float g_dt[BLn * NHh];                 // softplus(dt_raw + bias)
__device__ float g_cum[BLn * NHh];                // per-chunk cumsum of dt*A
__device__ float g_CB[NCT * QC * QC];             // per-chunk C.B^T gram
__device__ float g_states[(size_t)NCT * NHh * PD * NS];  // chunk states, then Sprev in-place
__device__ float g_y[(size_t)BLn * HIDC];         // y, then yn in-place

__device__ __forceinline__ void fma4(float4& a, float s, const float4 v) {
    a.x += s * v.x; a.y += s * v.y; a.z += s * v.z; a.w += s * v.w;
}

// =======================================================================
//  HYBRID GEMM: C[M,N] = A[M,K] * B[N,K]^T, fp32 in/out.
//  CTA tile 256x128, 512 threads:
//    warps 0-7 : fp16 mma.sync m16n8k16 on cols [0,64)   (tensor pipe)
//    warps 8-15: packed fp32 fma.rn.f32x2 on cols [64,128) (FMA pipe)
//  Both pipes run concurrently -> up to 256 MAC/cyc/SM.
// =======================================================================

__device__ __forceinline__ uint32_t pack_h2(float x, float y) {
    uint32_t r;
    asm("cvt.rn.f16x2.f32 %0, %1, %2;" : "=r"(r) : "f"(y), "f"(x));
    return r;
}
__device__ __forceinline__ void mma_f16(float* d, const uint32_t* a, const uint32_t* b) {
    asm volatile(
        "mma.sync.aligned.m16n8k16.row.col.f32.f16.f16.f32 "
        "{%0,%1,%2,%3}, {%4,%5,%6,%7}, {%8,%9}, {%0,%1,%2,%3};"
        : "+f"(d[0]), "+f"(d[1]), "+f"(d[2]), "+f"(d[3])
        : "r"(a[0]), "r"(a[1]), "r"(a[2]), "r"(a[3]), "r"(b[0]), "r"(b[1]));
}
__device__ __forceinline__ void ffma2(uint64_t& d, uint64_t a, uint64_t b) {
    asm("fma.rn.f32x2 %0, %1, %2, %0;" : "+l"(d) : "l"(a), "l"(b));
}
__device__ __forceinline__ uint64_t dup_f32(float v) {
    uint32_t u = __float_as_uint(v);
    return ((uint64_t)u << 32) | u;
}

// smem layout per stage (floats/halves):
#define AH    20                   // half stride for A_h/B_h rows
#define AHOFF 0                    // A_h: 256*20 halves = 10240 B
#define BHOFF 10240                // B_h: 64*20 halves  = 2560 B
#define AFOFF 12800                // A_f: 16 k * 770 floats = 49280 B (pre-paired (a,a), group 8 rows)
#define AFK   770
#define BFOFF (12800 + 49280)      // B_f: 16 k * 98 floats = 6272 B
#define BFK   98
#define STAGE (12800 + 49280 + 6272)   // 68352 B
#define HYB_SMEM (2 * STAGE)           // 136704 B

__global__ void __launch_bounds__(512) gemm_hyb(
    const float* __restrict__ A, const float* __restrict__ B, float* __restrict__ C,
    int Nvalid, int K, int ldC)
{
    extern __shared__ char smc[];
    const int tid  = threadIdx.x;
    const int wid  = tid >> 5, lane = tid & 31;
    const int cRow = blockIdx.y * 256;
    const int cCol = blockIdx.x * 128;
    const int KT   = K >> 4;

    // staging coords
    const int arow0 = tid >> 2;              // A rows (two loads: arow0, arow0+128)
    const int kq    = (tid & 3) * 4;         // k offset 0/4/8/12
    const int brow  = tid >> 2;              // B row 0..127 (only tids 0..511 -> rows via tid>>2 duplicated!)
    // NOTE: 512 threads, B has 128 rows x 4 k-quads = 512 slots: idx = tid -> row tid>>2, quad tid&3. OK.
    const bool bokv = (cCol + brow) < Nvalid;

    auto store_stage = [&](int slot, const float4* ra, float4 rbv) {
        char* sb = smc + slot * STAGE;
        __half* Ah = (__half*)(sb + AHOFF);
        __half* Bh = (__half*)(sb + BHOFF);
        float*  Af = (float*)(sb + AFOFF);
        float*  Bf = (float*)(sb + BFOFF);
        #pragma unroll
        for (int v = 0; v < 2; v++) {
            const int row = arow0 + v * 128;
            float vals[4] = { ra[v].x, ra[v].y, ra[v].z, ra[v].w };
            // fp16 copy
            uint2 pk = make_uint2(pack_h2(vals[0], vals[1]), pack_h2(vals[2], vals[3]));
            *reinterpret_cast<uint2*>(&Ah[row * AH + kq]) = pk;
            // fp32 pre-paired copy
            const int g = row >> 3, r2 = row & 7;
            #pragma unroll
            for (int j = 0; j < 4; j++) {
                *reinterpret_cast<uint64_t*>(&Af[(kq + j) * AFK + g * 24 + r2 * 2]) = dup_f32(vals[j]);
            }
        }
        {
            float vals[4] = { rbv.x, rbv.y, rbv.z, rbv.w };
            if (brow < 64) {
                uint2 pk = make_uint2(pack_h2(vals[0], vals[1]), pack_h2(vals[2], vals[3]));
                *reinterpret_cast<uint2*>(&Bh[brow * AH + kq]) = pk;
            } else {
                const int c = brow - 64, g = c >> 3, r2 = c & 7;
                #pragma unroll
                for (int j = 0; j < 4; j++)
                    Bf[(kq + j) * BFK + g * 12 + r2] = vals[j];
            }
        }
    };

    auto load_tile = [&](int kt, float4* ra, float4& rbv) {
        const int kb = kt << 4;
        #pragma unroll
        for (int v = 0; v < 2; v++)
            ra[v] = *reinterpret_cast<const float4*>(A + (size_t)(cRow + arow0 + v * 128) * K + kb + kq);
        rbv = bokv ? *reinterpret_cast<const float4*>(B + (size_t)(cCol + brow) * K + kb + kq)
                   : make_float4(0.f, 0.f, 0.f, 0.f);
    };

    // role-specific registers
    float accT[4][4][4];        // tensor warps
    uint64_t accF[8][4];        // ffma warps (each u64 = packed float2)
    if (wid < 8) {
        #pragma unroll
        for (int mi = 0; mi < 4; mi++)
            #pragma unroll
            for (int ni = 0; ni < 4; ni++)
                #pragma unroll
                for (int u = 0; u < 4; u++) accT[mi][ni][u] = 0.f;
    } else {
        #pragma unroll
        for (int i = 0; i < 8; i++)
            #pragma unroll
            for (int jj = 0; jj < 4; jj++) accF[i][jj] = 0ull;
    }

    const int gID = lane >> 2, tig = lane & 3;
    const int wM  = (wid >> 1) * 64;          // tensor warp M offset (wid 0-7)
    const int wN  = (wid & 1) * 32;           // tensor warp N offset
    const int ft  = tid - 256;                // ffma thread index (wid 8-15)
    const int tr  = (ft >> 3) & 31;           // ffma row group 0..31
    const int cg  = ft & 7;                   // ffma col group 0..7

    float4 ra[2]; float4 rbv;
    load_tile(0, ra, rbv);
    store_stage(0, ra, rbv);
    __syncthreads();

    for (int kt = 0; kt < KT; kt++) {
        const int b = kt & 1;
        const bool more = (kt + 1 < KT);
        if (more) load_tile(kt + 1, ra, rbv);

        const char* sb = smc + b * STAGE;
        if (wid < 8) {
            const __half* Ah = (const __half*)(sb + AHOFF);
            const __half* Bh = (const __half*)(sb + BHOFF);
            const int k0 = tig * 2;
            uint32_t af[4][4], bf[4][2];
            #pragma unroll
            for (int mi = 0; mi < 4; mi++) {
                const int r = wM + mi * 16 + gID;
                af[mi][0] = *reinterpret_cast<const uint32_t*>(&Ah[r * AH + k0]);
                af[mi][1] = *reinterpret_cast<const uint32_t*>(&Ah[(r + 8) * AH + k0]);
                af[mi][2] = *reinterpret_cast<const uint32_t*>(&Ah[r * AH + k0 + 8]);
                af[mi][3] = *reinterpret_cast<const uint32_t*>(&Ah[(r + 8) * AH + k0 + 8]);
            }
            #pragma unroll
            for (int ni = 0; ni < 4; ni++) {
                const int r = wN + ni * 8 + gID;
                bf[ni][0] = *reinterpret_cast<const uint32_t*>(&Bh[r * AH + k0]);
                bf[ni][1] = *reinterpret_cast<const uint32_t*>(&Bh[r * AH + k0 + 8]);
            }
            #pragma unroll
            for (int mi = 0; mi < 4; mi++)
                #pragma unroll
                for (int ni = 0; ni < 4; ni++)
                    mma_f16(accT[mi][ni], af[mi], bf[ni]);
        } else {
            const float* Af = (const float*)(sb + AFOFF);
            const float* Bf = (const float*)(sb + BFOFF);
            #pragma unroll
            for (int k = 0; k < 16; k++) {
                const uint64_t* ap = reinterpret_cast<const uint64_t*>(Af + k * AFK + tr * 24);
                const uint64_t* bp = reinterpret_cast<const uint64_t*>(Bf + k * BFK + cg * 12);
                uint64_t b0 = bp[0], b1 = bp[1], b2 = bp[2], b3 = bp[3];
                #pragma unroll
                for (int i = 0; i < 8; i++) {
                    uint64_t ai = ap[i];
                    ffma2(accF[i][0], ai, b0);
                    ffma2(accF[i][1], ai, b1);
                    ffma2(accF[i][2], ai, b2);
                    ffma2(accF[i][3], ai, b3);
                }
            }
        }

        if (more) store_stage(b ^ 1, ra, rbv);
        __syncthreads();
    }

    // epilogue
    if (wid < 8) {
        #pragma unroll
        for (int mi = 0; mi < 4; mi++) {
            const int r0 = cRow + wM + mi * 16 + gID;
            #pragma unroll
            for (int ni = 0; ni < 4; ni++) {
                const int c = cCol + wN + ni * 8 + tig * 2;
                if (c < Nvalid) {
                    *reinterpret_cast<float2*>(C + (size_t)r0 * ldC + c) =
                        make_float2(accT[mi][ni][0], accT[mi][ni][1]);
                    *reinterpret_cast<float2*>(C + (size_t)(r0 + 8) * ldC + c) =
                        make_float2(accT[mi][ni][2], accT[mi][ni][3]);
                }
            }
        }
    } else {
        const int cc = cCol + 64 + cg * 8;
        #pragma unroll
        for (int i = 0; i < 8; i++) {
            const int r = cRow + tr * 8 + i;
            #pragma unroll
            for (int jj = 0; jj < 4; jj++) {
                if (cc + jj * 2 < Nvalid)
                    *reinterpret_cast<uint64_t*>(C + (size_t)r * ldC + cc + jj * 2) = accF[i][jj];
            }
        }
    }
}

// ---------------- causal depthwise conv (K=4) + SiLU ----------------
__global__ void __launch_bounds__(256) conv_silu_kernel(const float* __restrict__ w) {
    size_t idx = (size_t)blockIdx.x * 256 + threadIdx.x;   // over BL*CONVD
    int c = (int)(idx % CONVD);
    int bl = (int)(idx / CONVD);
    int l = bl & (LSEQ - 1);
    float acc = 0.f;
    #pragma unroll
    for (int k = 0; k < 4; k++) {
        int lo = l - 3 + k;
        if (lo >= 0)
            acc += g_zx[(size_t)(bl - 3 + k) * DINn + HIDC + c] * w[c * 4 + k];
    }
    float s = 1.f / (1.f + expf(-acc));
    g_conv[(size_t)bl * CONVD + c] = acc * s;
}

// ---------------- dt = softplus(dt_raw + bias) ----------------
__global__ void __launch_bounds__(256) dt_kernel(const float* __restrict__ dt_bias) {
    int idx = blockIdx.x * 256 + threadIdx.x;    // over BL*NH
    int h = idx & 63;
    int bl = idx >> 6;
    float v = g_zx[(size_t)bl * DINn + (HIDC + CONVD) + h] + dt_bias[h];
    float d = (v > 20.f) ? v : log1pf(expf(v));
    g_dt[idx] = d;
}

// ---------------- per-chunk cumsum of dt*A (smem staged) ----------------
__global__ void __launch_bounds__(256) cum_kernel(const float* __restrict__ A_log) {
    __shared__ float s[QC * NHh];
    const int ch = blockIdx.x, tid = threadIdx.x;
    for (int idx = tid; idx < QC * NHh; idx += 256)
        s[idx] = g_dt[ch * QC * NHh + idx];
    __syncthreads();
    if (tid < NHh) {
        const float Ax = -expf(A_log[tid]);
        float run = 0.f;
        #pragma unroll 4
        for (int q = 0; q < QC; q++) {
            run += s[q * NHh + tid] * Ax;
            s[q * NHh + tid] = run;
        }
    }
    __syncthreads();
    for (int idx = tid; idx < QC * NHh; idx += 256)
        g_cum[ch * QC * NHh + idx] = s[idx];
}

// ---------------- per-chunk CB[i][j] = sum_n C[i,n]*B[j,n] ----------------
__global__ void __launch_bounds__(256) cb_kernel() {
    extern __shared__ float sh[];
    float* Bsh = sh;             // 128 x 129
    float* Csh = sh + 16512;     // 128 x 129
    int ch = blockIdx.x;
    int tid = threadIdx.x;
    for (int idx = tid; idx < 16384; idx += 256) {
        int i = idx >> 7, n = idx & 127;
        size_t row = (size_t)(ch * QC + i) * CONVD;
        Bsh[i * 129 + n] = g_conv[row + HIDC + n];
        Csh[i * 129 + n] = g_conv[row + HIDC + NS + n];
    }
    __syncthreads();
    int tx = tid & 15, ty = tid >> 4;
    float acc[8][8];
    #pragma unroll
    for (int i = 0; i < 8; i++)
        #pragma unroll
        for (int j = 0; j < 8; j++) acc[i][j] = 0.f;
    for (int n = 0; n < NS; n++) {
        float a[8], b[8];
        #pragma unroll
        for (int u = 0; u < 8; u++) a[u] = Csh[(ty * 8 + u) * 129 + n];
        #pragma unroll
        for (int u = 0; u < 8; u++) b[u] = Bsh[(tx * 8 + u) * 129 + n];
        #pragma unroll
        for (int i = 0; i < 8; i++)
            #pragma unroll
            for (int j = 0; j < 8; j++) acc[i][j] += a[i] * b[j];
    }
    #pragma unroll
    for (int i = 0; i < 8; i++)
        #pragma unroll
        for (int j0 = 0; j0 < 8; j0 += 4)
            *reinterpret_cast<float4*>(&g_CB[ch * 16384 + (ty * 8 + i) * 128 + tx * 8 + j0]) =
                make_float4(acc[i][j0], acc[i][j0 + 1], acc[i][j0 + 2], acc[i][j0 + 3]);
}

// ---------------- chunk states: states[h,p,n] = sum_q wdec[q]*xs[q,p]*B[q,n] ----------------
__global__ void __launch_bounds__(256) states_kernel() {
    __shared__ float Bs[32 * 128];
    __shared__ float xss[32 * 64];
    __shared__ float wdec[128];
    __shared__ float cl;
    const int h = blockIdx.x, ch = blockIdx.y;
    const int tid = threadIdx.x;
    if (tid == 0) cl = g_cum[(ch * QC + QC - 1) * NHh + h];
    __syncthreads();
    if (tid < 128) {
        int r = (ch * QC + tid) * NHh + h;
        wdec[tid] = __expf(cl - g_cum[r]) * g_dt[r];
    }
    const int p = tid >> 2, ng = tid & 3;
    float4 acc4[8];
    #pragma unroll
    for (int u = 0; u < 8; u++) acc4[u] = make_float4(0.f, 0.f, 0.f, 0.f);

    for (int qt = 0; qt < 4; qt++) {
        __syncthreads();
        for (int idx = tid; idx < 4096; idx += 256) {
            int qq = idx >> 7, n = idx & 127;
            Bs[idx] = g_conv[(size_t)(ch * QC + qt * 32 + qq) * CONVD + HIDC + n];
        }
        for (int idx = tid; idx < 2048; idx += 256) {
            int qq = idx >> 6, pp = idx & 63;
            xss[idx] = g_conv[(size_t)(ch * QC + qt * 32 + qq) * CONVD + h * PD + pp];
        }
        __syncthreads();
        #pragma unroll 4
        for (int qq = 0; qq < 32; qq++) {
            float coef = wdec[qt * 32 + qq] * xss[qq * 64 + p];
            const float4* bp = (const float4*)&Bs[qq * 128 + ng * 32];
            #pragma unroll
            for (int u = 0; u < 8; u++) fma4(acc4[u], coef, bp[u]);
        }
    }
    size_t base = ((size_t)ch * NHh + h) * (PD * NS) + (size_t)p * NS + ng * 32;
    #pragma unroll
    for (int u = 0; u < 8; u++)
        *reinterpret_cast<float4*>(&g_states[base + u * 4]) = acc4[u];
}

// ---------------- sequential inter-chunk scan (in-place: states -> Sprev) ----------------
__global__ void __launch_bounds__(256) scan_kernel() {
    const int h = blockIdx.x, b = blockIdx.y;
    const int t = threadIdx.x;
    float S[32];
    #pragma unroll
    for (int i = 0; i < 32; i++) S[i] = 0.f;
    for (int c = 0; c < 32; c++) {
        int ch = b * 32 + c;
        float dec = __expf(g_cum[(ch * QC + QC - 1) * NHh + h]);
        size_t base = ((size_t)ch * NHh + h) * (PD * NS);
        #pragma unroll
        for (int i = 0; i < 32; i++) {
            size_t id = base + (size_t)i * 256 + t;
            float st = g_states[id];
            g_states[id] = S[i];               // Sprev (state before this chunk)
            S[i] = S[i] * dec + st;
        }
    }
}

// ---------------- Yd + Yoff + D*xs -> y ----------------
__global__ void __launch_bounds__(256) ydyoff_kernel(const float* __restrict__ Dvec) {
    extern __shared__ float sh[];
    float* CBs   = sh;                 // 128 x 129
    float* Cs    = sh + 16512;         // 128 x 129
    float* SpT   = sh + 33024;         // [n][p] 128 x 64
    float* xss   = sh + 41216;         // [j][p] 128 x 64
    float* cum_s = sh + 49408;         // 128
    float* dt_s  = sh + 49536;         // 128
    const int h = blockIdx.x, ch = blockIdx.y, tid = threadIdx.x;

    for (int idx = tid; idx < 16384; idx += 256) {
        int i = idx >> 7, j = idx & 127;
        CBs[i * 129 + j] = g_CB[ch * 16384 + idx];
        Cs[i * 129 + j]  = g_conv[(size_t)(ch * QC + i) * CONVD + HIDC + NS + j];
    }
    for (int idx = tid; idx < 8192; idx += 256) {
        int p = idx >> 7, n = idx & 127;
        SpT[n * 64 + p] = g_states[((size_t)ch * NHh + h) * (PD * NS) + idx];
        xss[idx] = g_conv[(size_t)(ch * QC + (idx >> 6)) * CONVD + h * PD + (idx & 63)];
    }
    if (tid < 128) {
        int r = (ch * QC + tid) * NHh + h;
        cum_s[tid] = g_cum[r];
        dt_s[tid]  = g_dt[r];
    }
    __syncthreads();

    const int i = tid >> 1, ph = tid & 1;
    float4 aD[8], aO[8];
    #pragma unroll
    for (int u = 0; u < 8; u++) { aD[u] = make_float4(0.f,0.f,0.f,0.f); aO[u] = make_float4(0.f,0.f,0.f,0.f); }
    const float ci = cum_s[i];

    // intra-chunk (lower-triangular) attention
    for (int j = 0; j <= i; j++) {
        float m = CBs[i * 129 + j] * __expf(ci - cum_s[j]) * dt_s[j];
        const float4* xr = (const float4*)&xss[j * 64 + ph * 32];
        #pragma unroll
        for (int u = 0; u < 8; u++) fma4(aD[u], m, xr[u]);
    }
    // carried-state contribution
    #pragma unroll 4
    for (int n = 0; n < NS; n++) {
        float cv = Cs[i * 129 + n];
        const float4* sr = (const float4*)&SpT[n * 64 + ph * 32];
        #pragma unroll
        for (int u = 0; u < 8; u++) fma4(aO[u], cv, sr[u]);
    }
    const float ei = __expf(ci);
    const float Dh = Dvec[h];
    const float* xi = &xss[i * 64 + ph * 32];
    float* yo = &g_y[(size_t)(ch * QC + i) * HIDC + h * PD + ph * 32];
    #pragma unroll
    for (int u = 0; u < 8; u++) {
        float4 d = aD[u], o = aO[u];
        float4 r;
        r.x = d.x + ei * o.x + Dh * xi[u * 4 + 0];
        r.y = d.y + ei * o.y + Dh * xi[u * 4 + 1];
        r.z = d.z + ei * o.z + Dh * xi[u * 4 + 2];
        r.w = d.w + ei * o.w + Dh * xi[u * 4 + 3];
        *reinterpret_cast<float4*>(&yo[u * 4]) = r;
    }
}

// ---------------- gate with silu(z) + RMSNorm (in-place on g_y) ----------------
__global__ void __launch_bounds__(256) gating_kernel(const float* __restrict__ norm_w) {
    __shared__ float red[256];
    const int bl = blockIdx.x, tid = threadIdx.x;
    float vals[16];
    float ss = 0.f;
    #pragma unroll
    for (int it = 0; it < 16; it++) {
        int idx = it * 256 + tid;
        float yv = g_y[(size_t)bl * HIDC + idx];
        float z  = g_zx[(size_t)bl * DINn + idx];
        float yz = yv * (z / (1.f + expf(-z)));
        vals[it] = yz;
        ss += yz * yz;
    }
    red[tid] = ss;
    __syncthreads();
    for (int s = 128; s > 0; s >>= 1) {
        if (tid < s) red[tid] += red[tid + s];
        __syncthreads();
    }
    float sc = rsqrtf(red[0] / (float)HIDC + 1e-5f);
    #pragma unroll
    for (int it = 0; it < 16; it++) {
        int idx = it * 256 + tid;
        g_y[(size_t)bl * HIDC + idx] = vals[it] * sc * norm_w[idx];
    }
}

// ---------------- launch ----------------
extern "C" void kernel_launch(void* const* d_in, const int* in_sizes, int n_in,
                              void* d_out, int out_size) {
    const float* x       = (const float*)d_in[0];
    const float* W_in    = (const float*)d_in[1];
    const float* conv_w  = (const float*)d_in[2];
    const float* dt_bias = (const float*)d_in[3];
    const float* A_log   = (const float*)d_in[4];
    const float* Dv      = (const float*)d_in[5];
    const float* norm_w  = (const float*)d_in[6];
    const float* W_out   = (const float*)d_in[7];
    float* out = (float*)d_out;

    float *zx_p, *y_p;
    cudaGetSymbolAddress((void**)&zx_p, g_zx);
    cudaGetSymbolAddress((void**)&y_p, g_y);

    static cudaStream_t s2 = nullptr;
    static cudaEvent_t evA = nullptr, evB = nullptr;
    if (s2 == nullptr) {
        cudaStreamCreateWithFlags(&s2, cudaStreamNonBlocking);
        cudaEventCreateWithFlags(&evA, cudaEventDisableTiming);
        cudaEventCreateWithFlags(&evB, cudaEventDisableTiming);
        cudaFuncSetAttribute(gemm_hyb, cudaFuncAttributeMaxDynamicSharedMemorySize, HYB_SMEM);
        cudaFuncSetAttribute(cb_kernel, cudaFuncAttributeMaxDynamicSharedMemorySize, 132096);
        cudaFuncSetAttribute(ydyoff_kernel, cudaFuncAttributeMaxDynamicSharedMemorySize, 198656);
    }

    // 1a) in-proj GEMM, xBC+dt columns [4096, 8512)
    gemm_hyb<<<dim3(35, 32), 512, HYB_SMEM>>>(
        x, W_in + (size_t)HIDC * DIMI, zx_p + HIDC, DINn - HIDC, DIMI, DINn);
    cudaEventRecord(evA, 0);

    // 1b) in-proj GEMM, z columns [0, 4096) — side stream, overlapped with mid-chain
    cudaStreamWaitEvent(s2, evA, 0);
    gemm_hyb<<<dim3(32, 32), 512, HYB_SMEM, s2>>>(
        x, W_in, zx_p, HIDC, DIMI, DINn);
    cudaEventRecord(evB, s2);

    // mid-chain on default stream (concurrent with 1b)
    conv_silu_kernel<<<(BLn * CONVD) / 256, 256>>>(conv_w);
    dt_kernel<<<(BLn * NHh) / 256, 256>>>(dt_bias);
    cum_kernel<<<NCT, 256>>>(A_log);
    cb_kernel<<<NCT, 256, 132096>>>();
    states_kernel<<<dim3(NHh, NCT), 256>>>();
    scan_kernel<<<dim3(NHh, 2), 256>>>();
    ydyoff_kernel<<<dim3(NHh, NCT), 256, 198656>>>(Dv);

    // join: gating needs z columns from 1b
    cudaStreamWaitEvent(0, evB, 0);
    gating_kernel<<<BLn, 256>>>(norm_w);

    // 2) out-proj GEMM: (8192 x 4096) * (2048 x 4096)^T
    gemm_hyb<<<dim3(16, 32), 512, HYB_SMEM>>>(y_p, W_out, out, DIMI, HIDC, DIMI);
}